// round 13
// baseline (speedup 1.0000x reference)
#include <cuda_runtime.h>

#define B 512
#define T 512
#define H 128
#define G4 (4 * H)  // 512

// g_P stores P = 2^{min(2*log2e*w1e, 15)}  as [b][h/4][t'][h%4] float4 quads
__device__ float g_P[(size_t)B * H * T];

#define K2LOG2E 2.885390082f  // 2*log2(e)

__device__ __forceinline__ float ex2f(float x) {
    float r;
    asm("ex2.approx.f32 %0, %1;" : "=f"(r) : "f"(x));
    return r;
}
__device__ __forceinline__ float rcpf(float x) {
    float r;
    asm("rcp.approx.f32 %0, %1;" : "=f"(r) : "f"(x));
    return r;
}
__device__ __forceinline__ float copysign_bits(float mag, float sgn) {
    unsigned int m = __float_as_uint(mag) & 0x7fffffffu;
    unsigned int s = __float_as_uint(sgn) & 0x80000000u;
    return __uint_as_float(m | s);
}

// ---- gate tanh: negative-exponent safe form + Newton (accurate, NaN-proof) ----
__device__ __forceinline__ float tanh_safe(float x) {
    float y = x * K2LOG2E;
    float m = fminf(y, -y);         // -|y|
    float E = ex2f(m);              // e^{-2|x|} in (0,1]
    float den = E + 1.0f;
    float r = rcpf(den);
    r = r * fmaf(-den, r, 2.0f);    // Newton (den in [1,2], safe)
    float t = (1.0f - E) * r;
    return copysign_bits(t, x);
}

// ---------------- P = 2^{clamp(2log2e * (enc @ W1), <=15)}, transposed+interleaved ----------------
__global__ void __launch_bounds__(256) w1e_kernel(const float* __restrict__ enc,
                                                  const float* __restrict__ W1) {
    extern __shared__ float smem[];
    float* sW1 = smem;               // 128*128
    float* senc = smem + 128 * 128;  // 64 * 129 padded
    int tid = threadIdx.x;
    int b = blockIdx.x >> 3;
    int t0 = (blockIdx.x & 7) * 64;

    for (int i = tid; i < 128 * 128; i += 256) sW1[i] = W1[i];
    for (int i = tid; i < 64 * 128; i += 256) {
        int r = i >> 7, k = i & 127;
        senc[r * 129 + k] = enc[((size_t)b * T + t0 + r) * H + k];
    }
    __syncthreads();

    int t = tid & 63, hg = tid >> 6;
    float acc[32];
#pragma unroll
    for (int i = 0; i < 32; i++) acc[i] = 0.0f;
#pragma unroll 4
    for (int k = 0; k < 128; k++) {
        float e = senc[t * 129 + k];
        const float4* w4 = (const float4*)(sW1 + k * 128 + hg * 32);
#pragma unroll
        for (int q = 0; q < 8; q++) {
            float4 w = w4[q];
            acc[q * 4 + 0] = fmaf(e, w.x, acc[q * 4 + 0]);
            acc[q * 4 + 1] = fmaf(e, w.y, acc[q * 4 + 1]);
            acc[q * 4 + 2] = fmaf(e, w.z, acc[q * 4 + 2]);
            acc[q * 4 + 3] = fmaf(e, w.w, acc[q * 4 + 3]);
        }
    }
    float4* gp = (float4*)g_P;
#pragma unroll
    for (int i4 = 0; i4 < 8; i4++) {
        float4 o = make_float4(ex2f(fminf(acc[i4 * 4] * K2LOG2E, 15.0f)),
                               ex2f(fminf(acc[i4 * 4 + 1] * K2LOG2E, 15.0f)),
                               ex2f(fminf(acc[i4 * 4 + 2] * K2LOG2E, 15.0f)),
                               ex2f(fminf(acc[i4 * 4 + 3] * K2LOG2E, 15.0f)));
        gp[((size_t)b * 32 + hg * 8 + i4) * T + t0 + t] = o;
    }
}

// ---------------- persistent per-batch decoder: 256 threads, 2 t' per thread ----------------
__global__ void __launch_bounds__(256, 4) decoder_kernel(
    const float* __restrict__ x, const float* __restrict__ h0,
    const float* __restrict__ c0, const float* __restrict__ kern,
    const float* __restrict__ reck, const float* __restrict__ bias,
    const float* __restrict__ W2, const float* __restrict__ V,
    float* __restrict__ out) {
    __shared__ float sh[H];
    __shared__ float4 sEu4[32];     // Eu = 2^{u'} quads
    __shared__ float4 sv4[32];      // -2V quads
    __shared__ float sVs[H];
    __shared__ float4 spart4[512];  // phase A/C partials (8 KB, reused)
    __shared__ float sact[G4];      // gate activations
    __shared__ float sK0[G4], sK1[G4], sb[G4];
    __shared__ float sx[T * 2];
    __shared__ float sptr[2];
    __shared__ float s_sumV;
    __shared__ float rv[8];
    __shared__ int ri[8];

    int tid = threadIdx.x;
    int b = blockIdx.x;
    int lane = tid & 31, wid = tid >> 5;

    for (int i = tid; i < T * 2; i += 256) sx[i] = x[(size_t)b * T * 2 + i];
    sK0[tid] = kern[tid];
    sK0[tid + 256] = kern[tid + 256];
    sK1[tid] = kern[G4 + tid];
    sK1[tid + 256] = kern[G4 + tid + 256];
    sb[tid] = bias[tid];
    sb[tid + 256] = bias[tid + 256];
    if (tid < H) { sh[tid] = h0[b * H + tid]; sVs[tid] = V[tid]; }
    float creg = (tid < H) ? c0[b * H + tid] : 0.0f;
    if (tid == 0) { sptr[0] = 1.0f; sptr[1] = 1.0f; }
    __syncthreads();
    if (tid < H) ((float*)sv4)[tid] = -2.0f * sVs[tid];
    if (tid == 0) {
        float sv = 0.0f;
        for (int h = 0; h < H; h++) sv += sVs[h];
        s_sumV = sv;
    }
    __syncthreads();
    float sumV = s_sumV;

    const float4* wp4 = (const float4*)g_P + (size_t)b * 32 * T + tid;
    int r0 = tid, r1 = tid + 256;
    bool g_for_z1 = (tid < 128);  // z1 = gate tid+256 in [256,384) -> g-gate

    for (int s = 0; s < T; s++) {
        // ---- A: partial z, thread does 2 h-quarters of its gate quad: 64 x LDG.128 ----
        {
            int q = tid & 127;          // gate quad (float4 over 512 gates)
            int ph = (tid >> 7) * 2;    // quarters ph, ph+1
            const float4* rk = (const float4*)reck + q;
            const float4* sh4 = (const float4*)sh;
            float4 a0 = make_float4(0.f, 0.f, 0.f, 0.f);
            float4 a1 = make_float4(0.f, 0.f, 0.f, 0.f);
            const float4* rk0 = rk + (size_t)(ph * 32) * 128;
            const float4* rk1 = rk + (size_t)((ph + 1) * 32) * 128;
#pragma unroll
            for (int hq = 0; hq < 8; hq++) {
                float4 h0v = sh4[ph * 8 + hq];       // LDS.128 broadcast
                float4 h1v = sh4[(ph + 1) * 8 + hq];
                float4 w;
                w = __ldg(rk0 + (hq * 4 + 0) * 128);
                a0.x = fmaf(h0v.x, w.x, a0.x); a0.y = fmaf(h0v.x, w.y, a0.y);
                a0.z = fmaf(h0v.x, w.z, a0.z); a0.w = fmaf(h0v.x, w.w, a0.w);
                w = __ldg(rk0 + (hq * 4 + 1) * 128);
                a0.x = fmaf(h0v.y, w.x, a0.x); a0.y = fmaf(h0v.y, w.y, a0.y);
                a0.z = fmaf(h0v.y, w.z, a0.z); a0.w = fmaf(h0v.y, w.w, a0.w);
                w = __ldg(rk0 + (hq * 4 + 2) * 128);
                a0.x = fmaf(h0v.z, w.x, a0.x); a0.y = fmaf(h0v.z, w.y, a0.y);
                a0.z = fmaf(h0v.z, w.z, a0.z); a0.w = fmaf(h0v.z, w.w, a0.w);
                w = __ldg(rk0 + (hq * 4 + 3) * 128);
                a0.x = fmaf(h0v.w, w.x, a0.x); a0.y = fmaf(h0v.w, w.y, a0.y);
                a0.z = fmaf(h0v.w, w.z, a0.z); a0.w = fmaf(h0v.w, w.w, a0.w);
                w = __ldg(rk1 + (hq * 4 + 0) * 128);
                a1.x = fmaf(h1v.x, w.x, a1.x); a1.y = fmaf(h1v.x, w.y, a1.y);
                a1.z = fmaf(h1v.x, w.z, a1.z); a1.w = fmaf(h1v.x, w.w, a1.w);
                w = __ldg(rk1 + (hq * 4 + 1) * 128);
                a1.x = fmaf(h1v.y, w.x, a1.x); a1.y = fmaf(h1v.y, w.y, a1.y);
                a1.z = fmaf(h1v.y, w.z, a1.z); a1.w = fmaf(h1v.y, w.w, a1.w);
                w = __ldg(rk1 + (hq * 4 + 2) * 128);
                a1.x = fmaf(h1v.z, w.x, a1.x); a1.y = fmaf(h1v.z, w.y, a1.y);
                a1.z = fmaf(h1v.z, w.z, a1.z); a1.w = fmaf(h1v.z, w.w, a1.w);
                w = __ldg(rk1 + (hq * 4 + 3) * 128);
                a1.x = fmaf(h1v.w, w.x, a1.x); a1.y = fmaf(h1v.w, w.y, a1.y);
                a1.z = fmaf(h1v.w, w.z, a1.z); a1.w = fmaf(h1v.w, w.w, a1.w);
            }
            spart4[ph * 128 + q] = a0;
            spart4[(ph + 1) * 128 + q] = a1;
        }
        __syncthreads();

        // ---- B1: z-reduce + activation, 2 gates per thread ----
        {
            const float* sp = (const float*)spart4;
            float p0 = sptr[0], p1 = sptr[1];
#define ZRED(c) (fmaf(p1, sK1[c], fmaf(p0, sK0[c], sb[c])) \
                 + ((sp[(c)] + sp[512 + (c)]) + (sp[1024 + (c)] + sp[1536 + (c)])))
            float z0 = ZRED(r0);   // gates [0,256): i,f -> sigmoid
            float z1 = ZRED(r1);   // gates [256,512): g (tid<128) or o -> sigmoid
#undef ZRED
            float t0a = tanh_safe(0.5f * z0);
            sact[r0] = fmaf(0.5f, t0a, 0.5f);
            float t1a = tanh_safe(g_for_z1 ? z1 : 0.5f * z1);
            sact[r1] = g_for_z1 ? t1a : fmaf(0.5f, t1a, 0.5f);
        }
        __syncthreads();

        // ---- B2: cell update (threads 0..127) ----
        if (tid < H) {
            float c2 = sact[tid + H] * creg + sact[tid] * sact[tid + 2 * H];
            creg = c2;
            sh[tid] = sact[tid + 3 * H] * tanh_safe(c2);
        }
        __syncthreads();

        // ---- C: partial u, 2 tasks per thread (task = p2,g): 16 x LDG.128 ----
        {
#pragma unroll
            for (int k = 0; k < 2; k++) {
                int tk = tid + 256 * k;
                int p2 = tk >> 5, g = tk & 31;
                const float4* w2 = (const float4*)W2 + g;
                float4 a = make_float4(0.f, 0.f, 0.f, 0.f);
                int hb = p2 * 8;
#pragma unroll
                for (int h = 0; h < 8; h++) {
                    float hv = sh[hb + h];
                    float4 w = __ldg(w2 + (size_t)(hb + h) * 32);
                    a.x = fmaf(hv, w.x, a.x);
                    a.y = fmaf(hv, w.y, a.y);
                    a.z = fmaf(hv, w.z, a.z);
                    a.w = fmaf(hv, w.w, a.w);
                }
                spart4[tk] = a;
            }
        }
        __syncthreads();

        // ---- C-reduce: Eu[j] = 2^{clamp(u*2log2e)} (threads 0..127) ----
        if (tid < H) {
            const float* sp = (const float*)spart4;
            float u = 0.0f;
#pragma unroll
            for (int p2 = 0; p2 < 16; p2++) u += sp[p2 * 128 + tid];
            ((float*)sEu4)[tid] = ex2f(fminf(u * K2LOG2E, 15.0f));
        }
        __syncthreads();

        // ---- D: 2 t' per thread, 4-way combined rcp, d = P*Eu + 1 ----
        float accA = 0.0f, accB = 0.0f;
#pragma unroll 4
        for (int qd = 0; qd < 32; qd++) {
            float4 P0 = __ldcg(wp4 + (size_t)qd * T);
            float4 P1 = __ldcg(wp4 + (size_t)qd * T + 256);
            float4 Eu = sEu4[qd];
            float4 Vv = sv4[qd];
            // t' = tid
            float d0 = fmaf(P0.x, Eu.x, 1.0f);
            float d1 = fmaf(P0.y, Eu.y, 1.0f);
            float d2 = fmaf(P0.z, Eu.z, 1.0f);
            float d3 = fmaf(P0.w, Eu.w, 1.0f);
            float d01 = d0 * d1, d23 = d2 * d3;
            float n01 = Vv.x * d1; n01 = fmaf(Vv.y, d0, n01);
            float n23 = Vv.z * d3; n23 = fmaf(Vv.w, d2, n23);
            float num = n01 * d23; num = fmaf(n23, d01, num);
            accA = fmaf(num, rcpf(d01 * d23), accA);
            // t' = tid + 256
            float e0 = fmaf(P1.x, Eu.x, 1.0f);
            float e1 = fmaf(P1.y, Eu.y, 1.0f);
            float e2 = fmaf(P1.z, Eu.z, 1.0f);
            float e3 = fmaf(P1.w, Eu.w, 1.0f);
            float e01 = e0 * e1, e23 = e2 * e3;
            float m01 = Vv.x * e1; m01 = fmaf(Vv.y, e0, m01);
            float m23 = Vv.z * e3; m23 = fmaf(Vv.w, e2, m23);
            float mum = m01 * e23; mum = fmaf(m23, e01, mum);
            accB = fmaf(mum, rcpf(e01 * e23), accB);
        }
        float sc0 = sumV + accA;
        float sc1 = sumV + accB;
        size_t ob = ((size_t)b * T + s) * T;
        __stcs(out + ob + r0, sc0);
        __stcs(out + ob + r1, sc1);

        // ---- argmax (tie -> lowest index) + pointer select ----
        float best;
        int bidx;
        if (sc1 > sc0) { best = sc1; bidx = r1; }
        else           { best = sc0; bidx = r0; }
#pragma unroll
        for (int o = 16; o > 0; o >>= 1) {
            float ov = __shfl_xor_sync(0xffffffffu, best, o);
            int oi = __shfl_xor_sync(0xffffffffu, bidx, o);
            if (ov > best || (ov == best && oi < bidx)) { best = ov; bidx = oi; }
        }
        if (lane == 0) { rv[wid] = best; ri[wid] = bidx; }
        __syncthreads();
        if (wid == 0) {
            float bb = (lane < 8) ? rv[lane] : rv[0];
            int bi = (lane < 8) ? ri[lane] : ri[0];
#pragma unroll
            for (int o = 4; o > 0; o >>= 1) {
                float ov = __shfl_xor_sync(0xffffffffu, bb, o);
                int oi = __shfl_xor_sync(0xffffffffu, bi, o);
                if (ov > bb || (ov == bb && oi < bi)) { bb = ov; bi = oi; }
            }
            if (lane == 0) {
                sptr[0] = sx[bi * 2];
                sptr[1] = sx[bi * 2 + 1];
            }
        }
        __syncthreads();
    }
}

// ---------------- launch: 2 graph nodes ----------------
extern "C" void kernel_launch(void* const* d_in, const int* in_sizes, int n_in,
                              void* d_out, int out_size) {
    const float* x = (const float*)d_in[0];
    const float* enc = (const float*)d_in[1];
    const float* h0 = (const float*)d_in[2];
    const float* c0 = (const float*)d_in[3];
    const float* kern = (const float*)d_in[4];
    const float* reck = (const float*)d_in[5];
    const float* bias = (const float*)d_in[6];
    const float* W1 = (const float*)d_in[7];
    const float* W2 = (const float*)d_in[8];
    const float* V = (const float*)d_in[9];
    float* out = (float*)d_out;

    const int smem_w1e = (128 * 128 + 64 * 129) * 4;  // 98560 B
    cudaFuncSetAttribute(w1e_kernel, cudaFuncAttributeMaxDynamicSharedMemorySize, smem_w1e);
    w1e_kernel<<<B * 8, 256, smem_w1e>>>(enc, W1);
    decoder_kernel<<<B, 256>>>(x, h0, c0, kern, reck, bias, W2, V, out);
}